// round 8
// baseline (speedup 1.0000x reference)
#include <cuda_runtime.h>
#include <cstdint>
#include <cstddef>

#define NN 100000
#define NE 1600000
#define DD 128

// ---------------- scratch (device globals: no allocation allowed) ----------
__device__ float g_H[(size_t)NN * DD];   // holds h0, then Z2
__device__ float g_Z[(size_t)NN * DD];   // holds Z1
__device__ float g_sum1[DD], g_sq1[DD], g_sum2[DD], g_sq2[DD];
__device__ float g_scale1[DD], g_shift1[DD], g_scale2[DD], g_shift2[DD];
__device__ int   g_is64;

// ---------------- init: H = x (GIN eps = 0 -> (1+eps)*x = x) ---------------
__global__ void init_copy(const float4* __restrict__ x) {
    int i = blockIdx.x * blockDim.x + threadIdx.x;
    if (i < NN * DD / 4) ((float4*)g_H)[i] = x[i];
}

// ---------------- prep: zero stats + detect edge index dtype ---------------
__global__ void prep(const unsigned long long* __restrict__ ei) {
    int t = threadIdx.x;  // 128 threads
    g_sum1[t] = 0.f; g_sq1[t] = 0.f; g_sum2[t] = 0.f; g_sq2[t] = 0.f;
    if (t == 0) {
        // If data is int64, every value < NN. If int32, reading as u64 fuses
        // two random ints -> almost surely >= 2^32.
        int is64 = 1;
        for (int i = 0; i < 256; i++) {
            if (ei[i] >= (unsigned long long)NN) { is64 = 0; break; }
        }
        g_is64 = is64;
    }
}

// ---------------- scatter-add: H[dst] += x[src], one warp per edge ---------
__global__ void __launch_bounds__(256) scatter(const void* __restrict__ ei,
                                               const float4* __restrict__ x) {
    int e    = blockIdx.x * 8 + (threadIdx.x >> 5);
    int lane = threadIdx.x & 31;
    int src, dst;
    if (g_is64) {
        const long long* p = (const long long*)ei;
        src = (int)p[e];
        dst = (int)p[NE + e];
    } else {
        const int* p = (const int*)ei;
        src = p[e];
        dst = p[NE + e];
    }
    float4 v = __ldg(x + (size_t)src * 32 + lane);
    float* d = g_H + (size_t)dst * DD + lane * 4;
    asm volatile("red.global.add.v4.f32 [%0], {%1,%2,%3,%4};"
                 :: "l"(d), "f"(v.x), "f"(v.y), "f"(v.z), "f"(v.w)
                 : "memory");
}

// ---------------- fused GEMM: Z = transform(A) @ W^T (+bias) (+stats) ------
// mode 0: A used raw;            out = A@W^T + b;  accumulate col sum/sumsq
// mode 1: A' = relu(A*scale+sh); out = A'@W^T + b; accumulate col sum/sumsq
// mode 2: A' = relu(A*scale+sh); out = relu(A'@W^T)   (final layer, no bias)
// Tile: 128 rows x 128 cols x K=128, 256 threads, 8x8 per thread.
// Both A and W are stored k-major in smem ([k][idx]) with a 4-float XOR
// swizzle (idx ^ ((k>>2 & 7) << 2)) for conflict-free transposed stores.
__global__ void __launch_bounds__(256, 1) gemm(
    const float* __restrict__ A, const float* __restrict__ W,
    const float* __restrict__ bias,
    const float* __restrict__ scale, const float* __restrict__ shift,
    float* __restrict__ Z, float* __restrict__ gsum, float* __restrict__ gsq,
    int mode)
{
    extern __shared__ float sm[];
    float* AsT = sm;            // 128*128
    float* Bs  = sm + DD * DD;  // 128*128

    int tid = threadIdx.x;
    int rowBase = blockIdx.x * 128;

    // ---- load W[n][k] -> Bs[k][swz(n)] ----
    #pragma unroll
    for (int it = 0; it < 16; ++it) {
        int idx = it * 256 + tid;
        int n = idx >> 5, kq = idx & 31;
        float4 v = __ldg((const float4*)W + n * 32 + kq);
        int c = n ^ ((kq & 7) << 2);
        Bs[(4 * kq + 0) * DD + c] = v.x;
        Bs[(4 * kq + 1) * DD + c] = v.y;
        Bs[(4 * kq + 2) * DD + c] = v.z;
        Bs[(4 * kq + 3) * DD + c] = v.w;
    }
    // ---- load A[m][k] (with optional BN+ReLU) -> AsT[k][swz(m)] ----
    #pragma unroll
    for (int it = 0; it < 16; ++it) {
        int idx = it * 256 + tid;
        int m = idx >> 5, kq = idx & 31;
        int row = rowBase + m;
        float4 v = make_float4(0.f, 0.f, 0.f, 0.f);
        if (row < NN) v = __ldg((const float4*)A + (size_t)row * 32 + kq);
        if (mode != 0) {
            float4 s = __ldg((const float4*)scale + kq);
            float4 t = __ldg((const float4*)shift + kq);
            v.x = fmaxf(fmaf(v.x, s.x, t.x), 0.f);
            v.y = fmaxf(fmaf(v.y, s.y, t.y), 0.f);
            v.z = fmaxf(fmaf(v.z, s.z, t.z), 0.f);
            v.w = fmaxf(fmaf(v.w, s.w, t.w), 0.f);
        }
        int c = m ^ ((kq & 7) << 2);
        AsT[(4 * kq + 0) * DD + c] = v.x;
        AsT[(4 * kq + 1) * DD + c] = v.y;
        AsT[(4 * kq + 2) * DD + c] = v.z;
        AsT[(4 * kq + 3) * DD + c] = v.w;
    }
    __syncthreads();

    int tx = tid & 15, ty = tid >> 4;
    int m0 = ty * 8, n0 = tx * 8;

    float acc[8][8];
    #pragma unroll
    for (int i = 0; i < 8; i++)
        #pragma unroll
        for (int j = 0; j < 8; j++) acc[i][j] = 0.f;

    #pragma unroll 4
    for (int k = 0; k < DD; ++k) {
        int off = ((k >> 2) & 7) << 2;
        int s4 = off & 4;
        int ga = m0 ^ (off & 24);
        int gb = n0 ^ (off & 24);
        // positions ga+s4 .. +3 hold rows m0..m0+3; (^4) holds m0+4..m0+7
        float4 alo = *(const float4*)&AsT[k * DD + ga + s4];
        float4 ahi = *(const float4*)&AsT[k * DD + ((ga + s4) ^ 4)];
        float4 blo = *(const float4*)&Bs[k * DD + gb + s4];
        float4 bhi = *(const float4*)&Bs[k * DD + ((gb + s4) ^ 4)];
        float a[8] = {alo.x, alo.y, alo.z, alo.w, ahi.x, ahi.y, ahi.z, ahi.w};
        float b[8] = {blo.x, blo.y, blo.z, blo.w, bhi.x, bhi.y, bhi.z, bhi.w};
        #pragma unroll
        for (int i = 0; i < 8; i++)
            #pragma unroll
            for (int j = 0; j < 8; j++)
                acc[i][j] = fmaf(a[i], b[j], acc[i][j]);
    }

    if (mode == 2) {
        // final layer: out = relu(acc), no bias, no stats
        #pragma unroll
        for (int i = 0; i < 8; i++) {
            int row = rowBase + m0 + i;
            if (row < NN) {
                float4 o0, o1;
                o0.x = fmaxf(acc[i][0], 0.f); o0.y = fmaxf(acc[i][1], 0.f);
                o0.z = fmaxf(acc[i][2], 0.f); o0.w = fmaxf(acc[i][3], 0.f);
                o1.x = fmaxf(acc[i][4], 0.f); o1.y = fmaxf(acc[i][5], 0.f);
                o1.z = fmaxf(acc[i][6], 0.f); o1.w = fmaxf(acc[i][7], 0.f);
                *(float4*)(Z + (size_t)row * DD + n0)     = o0;
                *(float4*)(Z + (size_t)row * DD + n0 + 4) = o1;
            }
        }
    } else {
        float bv[8];
        {
            float4 b0 = __ldg((const float4*)bias + (n0 >> 2));
            float4 b1 = __ldg((const float4*)bias + (n0 >> 2) + 1);
            bv[0] = b0.x; bv[1] = b0.y; bv[2] = b0.z; bv[3] = b0.w;
            bv[4] = b1.x; bv[5] = b1.y; bv[6] = b1.z; bv[7] = b1.w;
        }
        float psum[8], psq[8];
        #pragma unroll
        for (int j = 0; j < 8; j++) { psum[j] = 0.f; psq[j] = 0.f; }

        #pragma unroll
        for (int i = 0; i < 8; i++) {
            int row = rowBase + m0 + i;
            float z[8];
            #pragma unroll
            for (int j = 0; j < 8; j++) z[j] = acc[i][j] + bv[j];
            if (row < NN) {
                float4 o0 = make_float4(z[0], z[1], z[2], z[3]);
                float4 o1 = make_float4(z[4], z[5], z[6], z[7]);
                *(float4*)(Z + (size_t)row * DD + n0)     = o0;
                *(float4*)(Z + (size_t)row * DD + n0 + 4) = o1;
                #pragma unroll
                for (int j = 0; j < 8; j++) {
                    psum[j] += z[j];
                    psq[j]  = fmaf(z[j], z[j], psq[j]);
                }
            }
        }
        // lane l <-> l+16 have the same columns (tx) -> pairwise reduce
        #pragma unroll
        for (int j = 0; j < 8; j++) {
            psum[j] += __shfl_xor_sync(0xffffffffu, psum[j], 16);
            psq[j]  += __shfl_xor_sync(0xffffffffu, psq[j], 16);
        }
        __syncthreads();  // smem reuse: compute reads are done
        float* ssum = sm;            // [8][128]
        float* ssq  = sm + 8 * DD;   // [8][128]
        int warp = tid >> 5, lane = tid & 31;
        if (lane < 16) {
            #pragma unroll
            for (int j = 0; j < 8; j++) {
                ssum[warp * DD + n0 + j] = psum[j];
                ssq [warp * DD + n0 + j] = psq[j];
            }
        }
        __syncthreads();
        if (tid < DD) {
            float s = 0.f;
            #pragma unroll
            for (int w = 0; w < 8; w++) s += ssum[w * DD + tid];
            atomicAdd(&gsum[tid], s);
        } else if (tid < 2 * DD) {
            int n = tid - DD;
            float s = 0.f;
            #pragma unroll
            for (int w = 0; w < 8; w++) s += ssq[w * DD + n];
            atomicAdd(&gsq[n], s);
        }
    }
}

// ---------------- fold BN into (scale, shift) -------------------------------
__global__ void finalize(const float* __restrict__ gsum, const float* __restrict__ gsq,
                         const float* __restrict__ gamma, const float* __restrict__ beta,
                         float* __restrict__ scale, float* __restrict__ shift) {
    int n = threadIdx.x;  // 128
    float mean = gsum[n] * (1.0f / NN);
    float var  = fmaxf(gsq[n] * (1.0f / NN) - mean * mean, 0.f);
    float sc   = gamma[n] * rsqrtf(var + 1e-5f);
    scale[n] = sc;
    shift[n] = beta[n] - mean * sc;
}

// ---------------- launch ----------------------------------------------------
extern "C" void kernel_launch(void* const* d_in, const int* in_sizes, int n_in,
                              void* d_out, int out_size) {
    const float* x   = (const float*)d_in[0];
    const void*  ei  = d_in[1];
    const float* W1  = (const float*)d_in[2];
    const float* b1  = (const float*)d_in[3];
    const float* g1  = (const float*)d_in[4];
    const float* be1 = (const float*)d_in[5];
    const float* W2  = (const float*)d_in[6];
    const float* b2  = (const float*)d_in[7];
    const float* g2  = (const float*)d_in[8];
    const float* be2 = (const float*)d_in[9];
    const float* W3  = (const float*)d_in[10];
    float* out = (float*)d_out;

    float *H, *Z, *s1, *q1, *s2, *q2, *sc1, *sh1, *sc2, *sh2;
    cudaGetSymbolAddress((void**)&H,   g_H);
    cudaGetSymbolAddress((void**)&Z,   g_Z);
    cudaGetSymbolAddress((void**)&s1,  g_sum1);
    cudaGetSymbolAddress((void**)&q1,  g_sq1);
    cudaGetSymbolAddress((void**)&s2,  g_sum2);
    cudaGetSymbolAddress((void**)&q2,  g_sq2);
    cudaGetSymbolAddress((void**)&sc1, g_scale1);
    cudaGetSymbolAddress((void**)&sh1, g_shift1);
    cudaGetSymbolAddress((void**)&sc2, g_scale2);
    cudaGetSymbolAddress((void**)&sh2, g_shift2);

    cudaFuncSetAttribute(gemm, cudaFuncAttributeMaxDynamicSharedMemorySize,
                         2 * DD * DD * (int)sizeof(float));

    // 1) H = x ; zero stats ; detect edge dtype
    init_copy<<<(NN * DD / 4 + 255) / 256, 256>>>((const float4*)x);
    prep<<<1, 128>>>((const unsigned long long*)ei);

    // 2) H[dst] += x[src]  (one warp per edge, vectorized red)
    scatter<<<NE / 8, 256>>>(ei, (const float4*)x);

    int gblocks = (NN + 127) / 128;  // 782
    size_t smem = 2 * DD * DD * sizeof(float);

    // 3) Z1 = H @ W1^T + b1, with column stats
    gemm<<<gblocks, 256, smem>>>(H, W1, b1, nullptr, nullptr, Z, s1, q1, 0);
    finalize<<<1, 128>>>(s1, q1, g1, be1, sc1, sh1);

    // 4) Z2 = relu(BN(Z1)) @ W2^T + b2, with column stats   (Z2 -> H buffer)
    gemm<<<gblocks, 256, smem>>>(Z, W2, b2, sc1, sh1, H, s2, q2, 1);
    finalize<<<1, 128>>>(s2, q2, g2, be2, sc2, sh2);

    // 5) out = relu( relu(BN(Z2)) @ W3^T )
    gemm<<<gblocks, 256, smem>>>(H, W3, nullptr, sc2, sh2, out, nullptr, nullptr, 2);
}

// round 10
// speedup vs baseline: 1.2108x; 1.2108x over previous
#include <cuda_runtime.h>
#include <cuda_bf16.h>
#include <cstdint>
#include <cstddef>

#define NN 100000
#define NE 1600000
#define DD 128
#define PITCHB 272   // bf16 tile row pitch in bytes (128*2 + 16): conflict-free ldmatrix

// ---------------- scratch (device globals: no allocation allowed) ----------
__device__ float g_H[(size_t)NN * DD];   // agg (then Z2)
__device__ float g_Z[(size_t)NN * DD];   // Z1
__device__ float g_sum1[DD], g_sq1[DD], g_sum2[DD], g_sq2[DD];
__device__ float g_scale1[DD], g_shift1[DD], g_scale2[DD], g_shift2[DD];
__device__ int   g_is64;

__device__ __forceinline__ uint32_t smem_u32(const void* p) {
    uint32_t a;
    asm("{ .reg .u64 t; cvta.to.shared.u64 t, %1; cvt.u32.u64 %0, t; }"
        : "=r"(a) : "l"(p));
    return a;
}

__device__ __forceinline__ void ldsm4(uint32_t* d, uint32_t addr) {
    asm volatile("ldmatrix.sync.aligned.m8n8.x4.shared.b16 {%0,%1,%2,%3}, [%4];"
                 : "=r"(d[0]), "=r"(d[1]), "=r"(d[2]), "=r"(d[3]) : "r"(addr));
}

__device__ __forceinline__ void mma16816(float* c, const uint32_t* a,
                                         uint32_t b0, uint32_t b1) {
    asm volatile(
        "mma.sync.aligned.m16n8k16.row.col.f32.bf16.bf16.f32 "
        "{%0,%1,%2,%3}, {%4,%5,%6,%7}, {%8,%9}, {%0,%1,%2,%3};"
        : "+f"(c[0]), "+f"(c[1]), "+f"(c[2]), "+f"(c[3])
        : "r"(a[0]), "r"(a[1]), "r"(a[2]), "r"(a[3]), "r"(b0), "r"(b1));
}

// ---------------- prep: zero stats + detect edge index dtype ---------------
__global__ void prep(const unsigned long long* __restrict__ ei) {
    int t = threadIdx.x;  // 128 threads
    g_sum1[t] = 0.f; g_sq1[t] = 0.f; g_sum2[t] = 0.f; g_sq2[t] = 0.f;
    if (t == 0) {
        // int64 edge data: every u64 word < NN. int32: two fused ints >= 2^32.
        int is64 = 1;
        for (int i = 0; i < 256; i++)
            if (ei[i] >= (unsigned long long)NN) { is64 = 0; break; }
        g_is64 = is64;
    }
}

// ---------------- scatter-add: H[dst] += x[src], one warp per edge ---------
__global__ void __launch_bounds__(256) scatter(const void* __restrict__ ei,
                                               const float4* __restrict__ x) {
    int e    = blockIdx.x * 8 + (threadIdx.x >> 5);
    int lane = threadIdx.x & 31;
    int src, dst;
    if (g_is64) {
        const long long* p = (const long long*)ei;
        src = (int)p[e];
        dst = (int)p[NE + e];
    } else {
        const int* p = (const int*)ei;
        src = p[e];
        dst = p[NE + e];
    }
    float4 v = __ldg(x + (size_t)src * 32 + lane);
    float* d = g_H + (size_t)dst * DD + lane * 4;
    asm volatile("red.global.add.v4.f32 [%0], {%1,%2,%3,%4};"
                 :: "l"(d), "f"(v.x), "f"(v.y), "f"(v.z), "f"(v.w)
                 : "memory");
}

// ======================= mma.sync fused GEMM ================================
// Z = transform(A) @ W^T (+bias) (+col stats), fp32 via bf16 hi/lo split:
//   A@W ~= Ahi@Whi + Ahi@Wlo + Alo@Whi  (fp32 accum in registers)
// mode 0: A' = A + A2 (x + agg);   out = A'@W^T + b; stats
// mode 1: A' = relu(A*sc+sh);      out = A'@W^T + b; stats
// mode 2: A' = relu(A*sc+sh);      out = relu(A'@W^T)
//
// smem: 4 bf16 tiles (Ahi, Alo, Whi, Wlo), 128 rows x 272B pitch each,
// then 2 x [4][128] fp32 stats staging.
#define TILE_B   (128 * PITCHB)          // 34816
#define SMO_SSUM (4 * TILE_B)
#define SMO_SSQ  (SMO_SSUM + 4 * DD * 4)
#define SMEM_BYTES (SMO_SSQ + 4 * DD * 4)

__device__ __forceinline__ void split_store(char* hi, char* lo,
                                            int row, int k4, float4 v) {
    int off = row * PITCHB + k4 * 8;
    __nv_bfloat162 h0 = __floats2bfloat162_rn(v.x, v.y);
    __nv_bfloat162 h1 = __floats2bfloat162_rn(v.z, v.w);
    float lx = v.x - __bfloat162float(h0.x);
    float ly = v.y - __bfloat162float(h0.y);
    float lz = v.z - __bfloat162float(h1.x);
    float lw = v.w - __bfloat162float(h1.y);
    __nv_bfloat162 l0 = __floats2bfloat162_rn(lx, ly);
    __nv_bfloat162 l1 = __floats2bfloat162_rn(lz, lw);
    *(uint2*)(hi + off) = make_uint2(*(uint32_t*)&h0, *(uint32_t*)&h1);
    *(uint2*)(lo + off) = make_uint2(*(uint32_t*)&l0, *(uint32_t*)&l1);
}

__global__ void __launch_bounds__(256, 1) gemm_mma(
    const float* __restrict__ A, const float* __restrict__ A2,
    const float* __restrict__ W, const float* __restrict__ bias,
    const float* __restrict__ scale, const float* __restrict__ shift,
    float* __restrict__ Z, float* __restrict__ gsum, float* __restrict__ gsq,
    int mode)
{
    extern __shared__ char sm[];
    char* Ahi = sm;
    char* Alo = sm + TILE_B;
    char* Whi = sm + 2 * TILE_B;
    char* Wlo = sm + 3 * TILE_B;
    float* sSum = (float*)(sm + SMO_SSUM);
    float* sSq  = (float*)(sm + SMO_SSQ);

    int tid = threadIdx.x;
    int rowBase = blockIdx.x * 128;

    // ---- W[n][k] fp32 -> bf16 hi/lo tiles (coalesced; one row per warp/iter)
    #pragma unroll
    for (int it = 0; it < 16; ++it) {
        int idx = it * 256 + tid;
        int n = idx >> 5, k4 = idx & 31;
        float4 v = __ldg((const float4*)W + n * 32 + k4);
        split_store(Whi, Wlo, n, k4, v);
    }
    // ---- A[m][k] fp32 (+transform) -> bf16 hi/lo tiles ----
    #pragma unroll
    for (int it = 0; it < 16; ++it) {
        int idx = it * 256 + tid;
        int m = idx >> 5, k4 = idx & 31;
        int row = rowBase + m;
        float4 v = make_float4(0.f, 0.f, 0.f, 0.f);
        if (row < NN) {
            v = __ldg((const float4*)A + (size_t)row * 32 + k4);
            if (mode == 0) {
                float4 u = __ldg((const float4*)A2 + (size_t)row * 32 + k4);
                v.x += u.x; v.y += u.y; v.z += u.z; v.w += u.w;
            } else {
                float4 s = __ldg((const float4*)scale + k4);
                float4 t = __ldg((const float4*)shift + k4);
                v.x = fmaxf(fmaf(v.x, s.x, t.x), 0.f);
                v.y = fmaxf(fmaf(v.y, s.y, t.y), 0.f);
                v.z = fmaxf(fmaf(v.z, s.z, t.z), 0.f);
                v.w = fmaxf(fmaf(v.w, s.w, t.w), 0.f);
            }
        }
        split_store(Ahi, Alo, m, k4, v);
    }
    __syncthreads();

    int wid = tid >> 5, lane = tid & 31;
    int mw = (wid >> 1) * 32;     // warp's row slab in tile
    int nw = (wid & 1) * 64;      // warp's col slab

    float acc[2][8][4];
    #pragma unroll
    for (int ms = 0; ms < 2; ms++)
        #pragma unroll
        for (int na = 0; na < 8; na++)
            #pragma unroll
            for (int j = 0; j < 4; j++) acc[ms][na][j] = 0.f;

    int r = lane & 7, sel = lane >> 3;
    const char* passA[3] = {Ahi, Ahi, Alo};
    const char* passW[3] = {Whi, Wlo, Whi};

    #pragma unroll
    for (int p = 0; p < 3; p++) {
        // ldmatrix lane addressing:
        //  A x4: mats {rows m0-7@k0, m8-15@k0, m0-7@k8, m8-15@k8}
        //  W x4: mats {rows n0-7@k0, n0-7@k8, n8-15@k0, n8-15@k8}
        uint32_t aAddr = smem_u32(passA[p]) +
            (uint32_t)((mw + r + (sel & 1) * 8) * PITCHB + (sel >> 1) * 16);
        uint32_t bAddr = smem_u32(passW[p]) +
            (uint32_t)((nw + r + (sel >> 1) * 8) * PITCHB + (sel & 1) * 16);
        #pragma unroll
        for (int ks = 0; ks < 8; ks++) {
            uint32_t ko = ks * 32;  // 16 bf16 = 32 bytes per K-step
            uint32_t a0[4], a1[4], b[4][4];
            ldsm4(a0, aAddr + ko);
            ldsm4(a1, aAddr + 16 * PITCHB + ko);
            #pragma unroll
            for (int ng = 0; ng < 4; ng++)
                ldsm4(b[ng], bAddr + ng * 16 * PITCHB + ko);
            #pragma unroll
            for (int na = 0; na < 8; na++) {
                uint32_t b0 = b[na >> 1][(na & 1) * 2];
                uint32_t b1 = b[na >> 1][(na & 1) * 2 + 1];
                mma16816(acc[0][na], a0, b0, b1);
                mma16816(acc[1][na], a1, b0, b1);
            }
        }
    }

    // ---- epilogue: D-fragment lane layout: c0,c1 -> (row l/4, col 2(l&3)+{0,1});
    //                                        c2,c3 -> (row l/4+8, same cols)
    int qr = lane >> 2, qc = lane & 3;
    if (mode == 2) {
        #pragma unroll
        for (int ms = 0; ms < 2; ms++) {
            int row0 = rowBase + mw + ms * 16 + qr;
            int row1 = row0 + 8;
            float* o0 = Z + (size_t)row0 * DD + nw + qc * 2;
            float* o1 = Z + (size_t)row1 * DD + nw + qc * 2;
            #pragma unroll
            for (int na = 0; na < 8; na++) {
                float* c = acc[ms][na];
                if (row0 < NN)
                    *(float2*)(o0 + na * 8) =
                        make_float2(fmaxf(c[0], 0.f), fmaxf(c[1], 0.f));
                if (row1 < NN)
                    *(float2*)(o1 + na * 8) =
                        make_float2(fmaxf(c[2], 0.f), fmaxf(c[3], 0.f));
            }
        }
    } else {
        float2 bv[8];
        #pragma unroll
        for (int na = 0; na < 8; na++)
            bv[na] = __ldg((const float2*)(bias + nw + na * 8 + qc * 2));

        float csum[16], csq[16];
        #pragma unroll
        for (int j = 0; j < 16; j++) { csum[j] = 0.f; csq[j] = 0.f; }

        #pragma unroll
        for (int ms = 0; ms < 2; ms++) {
            int row0 = rowBase + mw + ms * 16 + qr;
            int row1 = row0 + 8;
            bool ok0 = row0 < NN, ok1 = row1 < NN;
            float* o0 = Z + (size_t)row0 * DD + nw + qc * 2;
            float* o1 = Z + (size_t)row1 * DD + nw + qc * 2;
            #pragma unroll
            for (int na = 0; na < 8; na++) {
                float z0 = acc[ms][na][0] + bv[na].x;
                float z1 = acc[ms][na][1] + bv[na].y;
                float z2 = acc[ms][na][2] + bv[na].x;
                float z3 = acc[ms][na][3] + bv[na].y;
                if (ok0) *(float2*)(o0 + na * 8) = make_float2(z0, z1);
                if (ok1) *(float2*)(o1 + na * 8) = make_float2(z2, z3);
                float t0 = ok0 ? z0 : 0.f, t1 = ok0 ? z1 : 0.f;
                float t2 = ok1 ? z2 : 0.f, t3 = ok1 ? z3 : 0.f;
                csum[na * 2]     += t0 + t2;
                csum[na * 2 + 1] += t1 + t3;
                csq[na * 2]      += t0 * t0 + t2 * t2;
                csq[na * 2 + 1]  += t1 * t1 + t3 * t3;
            }
        }
        // reduce over the 8 row-quads (lanes differing in bits 2..4)
        #pragma unroll
        for (int mask = 4; mask <= 16; mask <<= 1) {
            #pragma unroll
            for (int j = 0; j < 16; j++) {
                csum[j] += __shfl_xor_sync(0xffffffffu, csum[j], mask);
                csq[j]  += __shfl_xor_sync(0xffffffffu, csq[j], mask);
            }
        }
        // lanes 0-3 hold per-column sums over this warp's 32 rows
        int g = wid >> 1;  // row-group; warps 2g / 2g+1 cover disjoint cols
        if (lane < 4) {
            #pragma unroll
            for (int na = 0; na < 8; na++) {
                int col = nw + na * 8 + lane * 2;
                sSum[g * DD + col]     = csum[na * 2];
                sSum[g * DD + col + 1] = csum[na * 2 + 1];
                sSq [g * DD + col]     = csq[na * 2];
                sSq [g * DD + col + 1] = csq[na * 2 + 1];
            }
        }
        __syncthreads();
        if (tid < DD) {
            float s = sSum[tid] + sSum[DD + tid] + sSum[2 * DD + tid] + sSum[3 * DD + tid];
            atomicAdd(&gsum[tid], s);
        } else if (tid < 2 * DD) {
            int n = tid - DD;
            float s = sSq[n] + sSq[DD + n] + sSq[2 * DD + n] + sSq[3 * DD + n];
            atomicAdd(&gsq[n], s);
        }
    }
}

// ---------------- fold BN into (scale, shift) -------------------------------
__global__ void finalize(const float* __restrict__ gsum, const float* __restrict__ gsq,
                         const float* __restrict__ gamma, const float* __restrict__ beta,
                         float* __restrict__ scale, float* __restrict__ shift) {
    int n = threadIdx.x;  // 128
    float mean = gsum[n] * (1.0f / NN);
    float var  = fmaxf(gsq[n] * (1.0f / NN) - mean * mean, 0.f);
    float sc   = gamma[n] * rsqrtf(var + 1e-5f);
    scale[n] = sc;
    shift[n] = beta[n] - mean * sc;
}

// ---------------- launch ----------------------------------------------------
extern "C" void kernel_launch(void* const* d_in, const int* in_sizes, int n_in,
                              void* d_out, int out_size) {
    const float* x   = (const float*)d_in[0];
    const void*  ei  = d_in[1];
    const float* W1  = (const float*)d_in[2];
    const float* b1  = (const float*)d_in[3];
    const float* g1  = (const float*)d_in[4];
    const float* be1 = (const float*)d_in[5];
    const float* W2  = (const float*)d_in[6];
    const float* b2  = (const float*)d_in[7];
    const float* g2  = (const float*)d_in[8];
    const float* be2 = (const float*)d_in[9];
    const float* W3  = (const float*)d_in[10];
    float* out = (float*)d_out;

    float *H, *Z, *s1, *q1, *s2, *q2, *sc1, *sh1, *sc2, *sh2;
    cudaGetSymbolAddress((void**)&H,   g_H);
    cudaGetSymbolAddress((void**)&Z,   g_Z);
    cudaGetSymbolAddress((void**)&s1,  g_sum1);
    cudaGetSymbolAddress((void**)&q1,  g_sq1);
    cudaGetSymbolAddress((void**)&s2,  g_sum2);
    cudaGetSymbolAddress((void**)&q2,  g_sq2);
    cudaGetSymbolAddress((void**)&sc1, g_scale1);
    cudaGetSymbolAddress((void**)&sh1, g_shift1);
    cudaGetSymbolAddress((void**)&sc2, g_scale2);
    cudaGetSymbolAddress((void**)&sh2, g_shift2);

    cudaFuncSetAttribute(gemm_mma, cudaFuncAttributeMaxDynamicSharedMemorySize,
                         SMEM_BYTES);

    // 1) H = 0 ; zero stats ; detect edge dtype
    cudaMemsetAsync(H, 0, (size_t)NN * DD * sizeof(float));
    prep<<<1, 128>>>((const unsigned long long*)ei);

    // 2) H[dst] += x[src]  (one warp per edge, vectorized red)
    scatter<<<NE / 8, 256>>>(ei, (const float4*)x);

    int gblocks = (NN + 127) / 128;  // 782

    // 3) Z1 = (x + H) @ W1^T + b1, with column stats
    gemm_mma<<<gblocks, 256, SMEM_BYTES>>>(x, H, W1, b1, nullptr, nullptr,
                                           Z, s1, q1, 0);
    finalize<<<1, 128>>>(s1, q1, g1, be1, sc1, sh1);

    // 4) Z2 = relu(BN(Z1)) @ W2^T + b2, with column stats  (Z2 -> H buffer)
    gemm_mma<<<gblocks, 256, SMEM_BYTES>>>(Z, nullptr, W2, b2, sc1, sh1,
                                           H, s2, q2, 1);
    finalize<<<1, 128>>>(s2, q2, g2, be2, sc2, sh2);

    // 5) out = relu( relu(BN(Z2)) @ W3^T )
    gemm_mma<<<gblocks, 256, SMEM_BYTES>>>(H, nullptr, W3, nullptr, sc2, sh2,
                                           out, nullptr, nullptr, 2);
}